// round 3
// baseline (speedup 1.0000x reference)
#include <cuda_runtime.h>
#include <cuda_bf16.h>

// Fixed problem shape: B=8, R=C=1024, instance ids in [0,16).
static constexpr int RDIM = 1024;
static constexpr int CDIM = 1024;
static constexpr int PER_BATCH = RDIM * CDIM;          // 2^20
static constexpr int BATCH = 8;
static constexpr int MAX_INST = 16;
static constexpr int NSLOT = BATCH * MAX_INST;         // 128

static constexpr int GRID = 148;                       // 1 CTA per SM, guaranteed resident
static constexpr int TPB  = 1024;
static constexpr int NVEC_TOTAL = (BATCH * PER_BATCH) / 4;        // 2,097,152 vec4
static constexpr int CHUNK = (NVEC_TOTAL + GRID - 1) / GRID;      // 14,170 vec4 per block
static constexpr int ITERS = (CHUNK + TPB - 1) / TPB;             // 14

// Per-block partial histograms (plain stores each launch — no zeroing needed)
// and a monotone epoch counter for the software grid barrier (replay-safe).
__device__ int g_part[GRID][NSLOT];
__device__ unsigned long long g_arrive;   // zero-initialized once at module load

__device__ __forceinline__ float sigmoidf_fast(float x) {
    return 1.0f / (1.0f + __expf(-x));
}

__global__ void __launch_bounds__(TPB, 1) pc_fused_kernel(
    const int*   __restrict__ nz,
    const float* __restrict__ pred,
    const float* __restrict__ off,     // (B, 2, R, C)
    const int*   __restrict__ gt,
    float*       __restrict__ out_pw,  // (B, R, C)
    float*       __restrict__ out_ow)  // (B, 2, R, C)
{
    __shared__ int   hist[NSLOT];
    __shared__ float inv_sh[NSLOT];

    const int tid = threadIdx.x;
    const int blk = blockIdx.x;
    const int vbase = blk * CHUNK;
    const int vend  = min(vbase + CHUNK, NVEC_TOTAL);

    for (int t = tid; t < NSLOT; t += TPB) hist[t] = 0;
    __syncthreads();

    // ---------------- Phase 1: count valid pixels per (batch, instance),
    // cache masked gt ids (4 pixels packed per uint) in registers. ----------
    unsigned int cache[ITERS];

    #pragma unroll
    for (int j = 0; j < ITERS; ++j) {
        const int v = vbase + j * TPB + tid;
        unsigned int packed = 0u;
        if (v < vend) {
            const long long i0 = (long long)v * 4;
            const int b = (int)(i0 >> 20);            // / PER_BATCH
            const int4 nz4 = *reinterpret_cast<const int4*>(nz + i0);
            const int4 gt4 = *reinterpret_cast<const int4*>(gt + i0);
            const int m0 = (nz4.x > 0 && gt4.x > 0) ? gt4.x : 0;
            const int m1 = (nz4.y > 0 && gt4.y > 0) ? gt4.y : 0;
            const int m2 = (nz4.z > 0 && gt4.z > 0) ? gt4.z : 0;
            const int m3 = (nz4.w > 0 && gt4.w > 0) ? gt4.w : 0;
            packed = (unsigned)m0 | ((unsigned)m1 << 8)
                   | ((unsigned)m2 << 16) | ((unsigned)m3 << 24);
            int* hb = &hist[b * MAX_INST];
            if (m0) atomicAdd(&hb[m0], 1);
            if (m1) atomicAdd(&hb[m1], 1);
            if (m2) atomicAdd(&hb[m2], 1);
            if (m3) atomicAdd(&hb[m3], 1);
        }
        cache[j] = packed;
    }
    __syncthreads();

    // Publish this block's partial histogram.
    for (int t = tid; t < NSLOT; t += TPB) g_part[blk][t] = hist[t];
    __threadfence();

    // ---------------- Software grid barrier (epoch-based, replay-safe) -----
    if (tid == 0) {
        unsigned long long old = atomicAdd(&g_arrive, 1ULL);
        unsigned long long target = (old / GRID) * GRID + GRID;
        while (*((volatile unsigned long long*)&g_arrive) < target) { }
    }
    __syncthreads();
    __threadfence();

    // Every block privately reduces the partial table -> shared inv_size.
    for (int t = tid; t < NSLOT; t += TPB) {
        int s = 0;
        #pragma unroll 4
        for (int kb = 0; kb < GRID; ++kb) s += g_part[kb][t];
        inv_sh[t] = 1.0f / fmaxf((float)s, 1.0f);
    }
    __syncthreads();

    // ---------------- Phase 2: per-pixel math, same pixel assignment -------
    #pragma unroll
    for (int j = 0; j < ITERS; ++j) {
        const int v = vbase + j * TPB + tid;
        if (v >= vend) continue;
        const long long i0 = (long long)v * 4;
        const int b   = (int)(i0 >> 20);
        const int rem = (int)(i0 & (PER_BATCH - 1));
        const int r   = rem >> 10;
        const int c0  = rem & (CDIM - 1);

        const float4 pr4 = *reinterpret_cast<const float4*>(pred + i0);
        const long long ob = ((long long)b * 2) * PER_BATCH + rem;
        const float4 oy4 = *reinterpret_cast<const float4*>(off + ob);
        const float4 ox4 = *reinterpret_cast<const float4*>(off + ob + PER_BATCH);

        const int* __restrict__ gt_b = gt + ((long long)b << 20);
        const float* __restrict__ inv_b = &inv_sh[b * MAX_INST];

        const unsigned int packed = cache[j];
        const float prs[4] = {pr4.x, pr4.y, pr4.z, pr4.w};
        const float oys[4] = {oy4.x, oy4.y, oy4.z, oy4.w};
        const float oxs[4] = {ox4.x, ox4.y, ox4.z, ox4.w};
        const float rf = (float)r;

        float pw[4], w0[4], w1[4];
        #pragma unroll
        for (int k = 0; k < 4; ++k) {
            const int g = (int)((packed >> (8 * k)) & 0xFFu);
            float w = 0.0f, agree_w = 0.0f;
            if (g) {
                w = inv_b[g];
                // round-half-to-even matches jnp.round
                float tyf = rintf(rf + oys[k]);
                float txf = rintf((float)(c0 + k) + oxs[k]);
                tyf = fminf(fmaxf(tyf, 0.0f), (float)(RDIM - 1));
                txf = fminf(fmaxf(txf, 0.0f), (float)(CDIM - 1));
                const int gtt = __ldg(&gt_b[((int)tyf << 10) + (int)txf]);
                agree_w = (gtt == g) ? w : 0.0f;
            }
            pw[k] = w * sigmoidf_fast(prs[k]);
            w0[k] = agree_w * oys[k];
            w1[k] = agree_w * oxs[k];
        }

        *reinterpret_cast<float4*>(out_pw + i0)             = make_float4(pw[0], pw[1], pw[2], pw[3]);
        *reinterpret_cast<float4*>(out_ow + ob)             = make_float4(w0[0], w0[1], w0[2], w0[3]);
        *reinterpret_cast<float4*>(out_ow + ob + PER_BATCH) = make_float4(w1[0], w1[1], w1[2], w1[3]);
    }
}

extern "C" void kernel_launch(void* const* d_in, const int* in_sizes, int n_in,
                              void* d_out, int out_size) {
    const int*   nz   = (const int*)  d_in[0];  // non_zeros_map (B,R,C) int32
    const float* pred = (const float*)d_in[1];  // pixel_pred    (B,R,C) f32
    const float* off  = (const float*)d_in[2];  // offset_pred   (B,2,R,C) f32
    const int*   gt   = (const int*)  d_in[3];  // pixel_gt      (B,R,C) int32

    const long long N = in_sizes[0];            // B*R*C
    float* out_pw = (float*)d_out;
    float* out_ow = (float*)d_out + N;

    pc_fused_kernel<<<GRID, TPB>>>(nz, pred, off, gt, out_pw, out_ow);
}

// round 4
// speedup vs baseline: 1.1832x; 1.1832x over previous
#include <cuda_runtime.h>
#include <cuda_bf16.h>

// Fixed problem shape: B=8, R=C=1024, instance ids in [0,16).
static constexpr int RDIM = 1024;
static constexpr int CDIM = 1024;
static constexpr int PER_BATCH = RDIM * CDIM;          // 2^20
static constexpr int BATCH = 8;
static constexpr int MAX_INST = 16;
static constexpr int NSLOT = BATCH * MAX_INST;         // 128
static constexpr int NPIX = BATCH * PER_BATCH;         // 2^23
static constexpr int NVEC = NPIX / 4;                  // 2,097,152

// Kernel 1 geometry (persistent-ish: 1 CTA/SM)
static constexpr int GRID1 = 148;
static constexpr int TPB1  = 1024;
static constexpr int CHUNK1 = (NVEC + GRID1 - 1) / GRID1;   // 14,170
// Kernel 3 geometry
static constexpr int TPB3 = 256;
static constexpr int GRID3 = NVEC / TPB3;                   // 8192

// Scratch (static device globals — no allocation). Plain-stored every run,
// so no zeroing pass and no global atomics are required.
__device__ int           g_part[GRID1][NSLOT];
__device__ float         g_inv[NSLOT];
__device__ unsigned char g_mask[NPIX];                      // 8 MB

__device__ __forceinline__ float sigmoidf_fast(float x) {
    return 1.0f / (1.0f + __expf(-x));
}

// ---- Kernel 1: count valid pixels per (batch, instance); emit uint8 mask ----
__global__ void __launch_bounds__(TPB1, 1) pc_count_kernel(
    const int* __restrict__ nz, const int* __restrict__ gt)
{
    __shared__ int hist[NSLOT];
    const int tid = threadIdx.x;
    const int blk = blockIdx.x;
    for (int t = tid; t < NSLOT; t += TPB1) hist[t] = 0;
    __syncthreads();

    const int vbase = blk * CHUNK1;
    const int vend  = min(vbase + CHUNK1, NVEC);

    for (int v = vbase + tid; v < vend; v += TPB1) {
        const long long i0 = (long long)v * 4;
        const int b16 = (int)(i0 >> 20) * MAX_INST;       // batch * 16
        const int4 nz4 = *reinterpret_cast<const int4*>(nz + i0);
        const int4 gt4 = *reinterpret_cast<const int4*>(gt + i0);
        const int m0 = (nz4.x > 0 && gt4.x > 0) ? gt4.x : 0;
        const int m1 = (nz4.y > 0 && gt4.y > 0) ? gt4.y : 0;
        const int m2 = (nz4.z > 0 && gt4.z > 0) ? gt4.z : 0;
        const int m3 = (nz4.w > 0 && gt4.w > 0) ? gt4.w : 0;
        const unsigned int packed = (unsigned)m0 | ((unsigned)m1 << 8)
                                  | ((unsigned)m2 << 16) | ((unsigned)m3 << 24);
        *reinterpret_cast<unsigned int*>(g_mask + i0) = packed;
        if (m0) atomicAdd(&hist[b16 + m0], 1);
        if (m1) atomicAdd(&hist[b16 + m1], 1);
        if (m2) atomicAdd(&hist[b16 + m2], 1);
        if (m3) atomicAdd(&hist[b16 + m3], 1);
    }
    __syncthreads();
    if (tid < NSLOT) g_part[blk][tid] = hist[tid];
}

// ---- Kernel 2: reduce 148 partial histograms -> inv_size table ----
__global__ void __launch_bounds__(1024) pc_reduce_kernel()
{
    __shared__ int partial[1024];
    const int tid  = threadIdx.x;
    const int slot = tid >> 3;       // 128 slots
    const int lane = tid & 7;        // 8 lanes per slot
    int s = 0;
    #pragma unroll 4
    for (int kb = lane; kb < GRID1; kb += 8) s += g_part[kb][slot];
    partial[tid] = s;
    __syncthreads();
    if (lane == 0) {
        int tot = 0;
        #pragma unroll
        for (int l = 0; l < 8; ++l) tot += partial[(slot << 3) + l];
        g_inv[slot] = 1.0f / fmaxf((float)tot, 1.0f);
    }
}

// ---- Kernel 3: per-pixel weights; mask replaces nz/gt re-read ----
__global__ void __launch_bounds__(TPB3) pc_main_kernel(
    const float* __restrict__ pred,
    const float* __restrict__ off,     // (B, 2, R, C)
    const int*   __restrict__ gt,
    float*       __restrict__ out_pw,  // (B, R, C)
    float*       __restrict__ out_ow)  // (B, 2, R, C)
{
    const int v = blockIdx.x * TPB3 + threadIdx.x;
    const long long i0 = (long long)v * 4;
    const int b   = (int)(i0 >> 20);
    const int rem = (int)(i0 & (PER_BATCH - 1));
    const int r   = rem >> 10;
    const int c0  = rem & (CDIM - 1);

    const unsigned int packed = *reinterpret_cast<const unsigned int*>(g_mask + i0);
    const float4 pr4 = *reinterpret_cast<const float4*>(pred + i0);
    const long long ob = ((long long)b * 2) * PER_BATCH + rem;
    const float4 oy4 = *reinterpret_cast<const float4*>(off + ob);
    const float4 ox4 = *reinterpret_cast<const float4*>(off + ob + PER_BATCH);

    const int* __restrict__ gt_b = gt + ((long long)b << 20);
    const float* __restrict__ inv_b = g_inv + b * MAX_INST;

    const float prs[4] = {pr4.x, pr4.y, pr4.z, pr4.w};
    const float oys[4] = {oy4.x, oy4.y, oy4.z, oy4.w};
    const float oxs[4] = {ox4.x, ox4.y, ox4.z, ox4.w};
    const float rf = (float)r;

    float pw[4], w0[4], w1[4];
    #pragma unroll
    for (int k = 0; k < 4; ++k) {
        const int g = (int)((packed >> (8 * k)) & 0xFFu);
        float w = 0.0f, agree_w = 0.0f;
        if (g) {
            w = __ldg(&inv_b[g]);
            // round-half-to-even matches jnp.round
            float tyf = rintf(rf + oys[k]);
            float txf = rintf((float)(c0 + k) + oxs[k]);
            tyf = fminf(fmaxf(tyf, 0.0f), (float)(RDIM - 1));
            txf = fminf(fmaxf(txf, 0.0f), (float)(CDIM - 1));
            const int gtt = __ldg(&gt_b[((int)tyf << 10) + (int)txf]);
            agree_w = (gtt == g) ? w : 0.0f;
        }
        pw[k] = w * sigmoidf_fast(prs[k]);
        w0[k] = agree_w * oys[k];
        w1[k] = agree_w * oxs[k];
    }

    *reinterpret_cast<float4*>(out_pw + i0)             = make_float4(pw[0], pw[1], pw[2], pw[3]);
    *reinterpret_cast<float4*>(out_ow + ob)             = make_float4(w0[0], w0[1], w0[2], w0[3]);
    *reinterpret_cast<float4*>(out_ow + ob + PER_BATCH) = make_float4(w1[0], w1[1], w1[2], w1[3]);
}

extern "C" void kernel_launch(void* const* d_in, const int* in_sizes, int n_in,
                              void* d_out, int out_size) {
    const int*   nz   = (const int*)  d_in[0];  // non_zeros_map (B,R,C) int32
    const float* pred = (const float*)d_in[1];  // pixel_pred    (B,R,C) f32
    const float* off  = (const float*)d_in[2];  // offset_pred   (B,2,R,C) f32
    const int*   gt   = (const int*)  d_in[3];  // pixel_gt      (B,R,C) int32

    const long long N = in_sizes[0];            // B*R*C
    float* out_pw = (float*)d_out;
    float* out_ow = (float*)d_out + N;

    pc_count_kernel<<<GRID1, TPB1>>>(nz, gt);
    pc_reduce_kernel<<<1, 1024>>>();
    pc_main_kernel<<<GRID3, TPB3>>>(pred, off, gt, out_pw, out_ow);
}

// round 5
// speedup vs baseline: 1.3901x; 1.1749x over previous
#include <cuda_runtime.h>
#include <cuda_bf16.h>

// Fixed problem shape: B=8, R=C=1024, instance ids in [0,16).
static constexpr int RDIM = 1024;
static constexpr int CDIM = 1024;
static constexpr int PER_BATCH = RDIM * CDIM;            // 2^20 pixels
static constexpr int BATCH = 8;
static constexpr int MAX_INST = 16;
static constexpr int NPIX = BATCH * PER_BATCH;           // 2^23
static constexpr int NVEC_B = PER_BATCH / 4;             // 262144 vec4 per batch

// Kernel 1: batch-pure blocks, grid (18, 8) = 144 blocks (one wave on 148 SMs)
static constexpr int BLKS_PER_B = 18;
static constexpr int TPB1 = 1024;
static constexpr int CHUNK1 = (NVEC_B + BLKS_PER_B - 1) / BLKS_PER_B;  // 14564
// Kernel 3
static constexpr int TPB3 = 256;
static constexpr int GRID3 = (NPIX / 4) / TPB3;          // 8192

// Scratch (static device globals). Plain-stored every launch — replay-safe.
__device__ int           g_part[BATCH * BLKS_PER_B][MAX_INST];
__device__ float         g_inv[BATCH * MAX_INST];
__device__ unsigned char g_plane[NPIX];   // byte = raw_gt | (valid << 4)

__device__ __forceinline__ float sigmoidf_fast(float x) {
    return 1.0f / (1.0f + __expf(-x));
}

// ---- Kernel 1: atomic-free per-(batch,instance) counts + combined byte plane
__global__ void __launch_bounds__(TPB1, 1) pc_count_kernel(
    const int* __restrict__ nz, const int* __restrict__ gt)
{
    __shared__ unsigned long long wcnt[32][4];

    const int tid  = threadIdx.x;
    const int wid  = tid >> 5;
    const int lane = tid & 31;
    const int b    = blockIdx.y;
    const int vbase = blockIdx.x * CHUNK1;
    const int vend  = min(vbase + CHUNK1, NVEC_B);
    const long long batch_off = (long long)b << 20;

    // byte-packed per-thread counters: ids 0..7 in lo, 8..15 in hi
    unsigned long long lo = 0ULL, hi = 0ULL;

    for (int v = vbase + tid; v < vend; v += TPB1) {
        const long long i0 = batch_off + (long long)v * 4;
        const int4 nz4 = *reinterpret_cast<const int4*>(nz + i0);
        const int4 gt4 = *reinterpret_cast<const int4*>(gt + i0);

        const int gts[4] = {gt4.x, gt4.y, gt4.z, gt4.w};
        const int nzs[4] = {nz4.x, nz4.y, nz4.z, nz4.w};
        unsigned int packed = 0u;
        #pragma unroll
        for (int k = 0; k < 4; ++k) {
            const int g = gts[k];
            const bool valid = (nzs[k] > 0) && (g > 0);
            packed |= ((unsigned)g | (valid ? 0x10u : 0u)) << (8 * k);
            const int m = valid ? g : 0;     // id 0 counter is a harmless sink
            const unsigned long long inc = 1ULL << ((m & 7) * 8);
            if (m < 8) lo += inc; else hi += inc;
        }
        *reinterpret_cast<unsigned int*>(g_plane + i0) = packed;
    }

    // Expand byte counters to 16-bit fields (max 60*32=1920 per field < 65535)
    const unsigned long long M = 0x00FF00FF00FF00FFULL;
    unsigned long long v0 = lo & M;          // ids 0,2,4,6
    unsigned long long v1 = (lo >> 8) & M;   // ids 1,3,5,7
    unsigned long long v2 = hi & M;          // ids 8,10,12,14
    unsigned long long v3 = (hi >> 8) & M;   // ids 9,11,13,15

    #pragma unroll
    for (int s = 16; s > 0; s >>= 1) {
        v0 += __shfl_xor_sync(0xffffffffu, v0, s);
        v1 += __shfl_xor_sync(0xffffffffu, v1, s);
        v2 += __shfl_xor_sync(0xffffffffu, v2, s);
        v3 += __shfl_xor_sync(0xffffffffu, v3, s);
    }
    if (lane == 0) {
        wcnt[wid][0] = v0; wcnt[wid][1] = v1; wcnt[wid][2] = v2; wcnt[wid][3] = v3;
    }
    __syncthreads();

    if (tid < MAX_INST) {
        const int id = tid;
        const int vec   = (((id >= 8) ? 2 : 0) | (id & 1));
        const int shift = ((id & 7) >> 1) * 16;
        int s = 0;
        #pragma unroll 4
        for (int w = 0; w < 32; ++w)
            s += (int)((wcnt[w][vec] >> shift) & 0xFFFFULL);
        g_part[b * BLKS_PER_B + blockIdx.x][id] = s;
    }
}

// ---- Kernel 2: reduce 18 partial histograms per batch -> inv_size table ----
__global__ void __launch_bounds__(128) pc_reduce_kernel()
{
    const int tid = threadIdx.x;          // 0..127 = b*16 + id
    const int b = tid >> 4, id = tid & 15;
    int s = 0;
    #pragma unroll
    for (int k = 0; k < BLKS_PER_B; ++k) s += g_part[b * BLKS_PER_B + k][id];
    g_inv[tid] = 1.0f / fmaxf((float)s, 1.0f);
}

// ---- Kernel 3: per-pixel weights; combined plane for stream AND gather ----
__global__ void __launch_bounds__(TPB3) pc_main_kernel(
    const float* __restrict__ pred,
    const float* __restrict__ off,     // (B, 2, R, C)
    float*       __restrict__ out_pw,  // (B, R, C)
    float*       __restrict__ out_ow)  // (B, 2, R, C)
{
    const int v = blockIdx.x * TPB3 + threadIdx.x;
    const long long i0 = (long long)v * 4;
    const int b   = (int)(i0 >> 20);
    const int rem = (int)(i0 & (PER_BATCH - 1));
    const int r   = rem >> 10;
    const int c0  = rem & (CDIM - 1);

    const unsigned int packed = *reinterpret_cast<const unsigned int*>(g_plane + i0);
    const float4 pr4 = *reinterpret_cast<const float4*>(pred + i0);
    const long long ob = ((long long)b * 2) * PER_BATCH + rem;
    const float4 oy4 = *reinterpret_cast<const float4*>(off + ob);
    const float4 ox4 = *reinterpret_cast<const float4*>(off + ob + PER_BATCH);

    const unsigned char* __restrict__ plane_b = g_plane + ((long long)b << 20);
    const float* __restrict__ inv_b = g_inv + b * MAX_INST;

    const float prs[4] = {pr4.x, pr4.y, pr4.z, pr4.w};
    const float oys[4] = {oy4.x, oy4.y, oy4.z, oy4.w};
    const float oxs[4] = {ox4.x, ox4.y, ox4.z, ox4.w};
    const float rf = (float)r;

    float pw[4], w0[4], w1[4];
    #pragma unroll
    for (int k = 0; k < 4; ++k) {
        const unsigned s = (packed >> (8 * k)) & 0xFFu;
        const int g = (int)(s & 0xFu);
        float w = 0.0f, agree_w = 0.0f;
        if (s & 0x10u) {                         // valid
            w = __ldg(&inv_b[g]);
            // round-half-to-even matches jnp.round
            float tyf = rintf(rf + oys[k]);
            float txf = rintf((float)(c0 + k) + oxs[k]);
            tyf = fminf(fmaxf(tyf, 0.0f), (float)(RDIM - 1));
            txf = fminf(fmaxf(txf, 0.0f), (float)(CDIM - 1));
            const unsigned tb = __ldg(&plane_b[((int)tyf << 10) + (int)txf]);
            agree_w = ((int)(tb & 0xFu) == g) ? w : 0.0f;
        }
        pw[k] = w * sigmoidf_fast(prs[k]);
        w0[k] = agree_w * oys[k];
        w1[k] = agree_w * oxs[k];
    }

    *reinterpret_cast<float4*>(out_pw + i0)             = make_float4(pw[0], pw[1], pw[2], pw[3]);
    *reinterpret_cast<float4*>(out_ow + ob)             = make_float4(w0[0], w0[1], w0[2], w0[3]);
    *reinterpret_cast<float4*>(out_ow + ob + PER_BATCH) = make_float4(w1[0], w1[1], w1[2], w1[3]);
}

extern "C" void kernel_launch(void* const* d_in, const int* in_sizes, int n_in,
                              void* d_out, int out_size) {
    const int*   nz   = (const int*)  d_in[0];  // non_zeros_map (B,R,C) int32
    const float* pred = (const float*)d_in[1];  // pixel_pred    (B,R,C) f32
    const float* off  = (const float*)d_in[2];  // offset_pred   (B,2,R,C) f32
    const int*   gt   = (const int*)  d_in[3];  // pixel_gt      (B,R,C) int32

    const long long N = in_sizes[0];            // B*R*C
    float* out_pw = (float*)d_out;
    float* out_ow = (float*)d_out + N;

    dim3 grid1(BLKS_PER_B, BATCH);
    pc_count_kernel<<<grid1, TPB1>>>(nz, gt);
    pc_reduce_kernel<<<1, 128>>>();
    pc_main_kernel<<<GRID3, TPB3>>>(pred, off, out_pw, out_ow);
}